// round 8
// baseline (speedup 1.0000x reference)
#include <cuda_runtime.h>
#include <cstdint>
#include <cstddef>

#define LL 32
#define HH 128
#define SPB 4
#define NBLK 128
#define NTHR 512
#define NCELL 1024
#define EPSF 1e-8f

#define W_STAGE_BYTES 65536u
#define AUX_STAGE_BYTES 2048u
#define TX_BYTES (W_STAGE_BYTES + AUX_STAGE_BYTES)

#define OFF_W    0u
#define OFF_AUX  131072u
#define OFF_HV   135168u
#define OFF_PRE  200704u
#define OFF_INP  217088u
#define OFF_RED2 219136u
#define OFF_RED3 227328u
#define OFF_SB4  227456u
#define OFF_MBAR 227968u
#define SMEM_SZ  228000u

typedef unsigned long long ull;
struct __align__(16) u64x2 { ull x, y; };

__device__ float g_Wq[(size_t)NCELL * 16384];   // swizzled [cell][kq][n][slot][4]
__device__ float g_aux[(size_t)NCELL * 512];    // [cell][{w0,w1,b,wf}][n]

__device__ __forceinline__ uint32_t s2u(const void* p) {
    return (uint32_t)__cvta_generic_to_shared(p);
}
__device__ __forceinline__ void mbar_init(uint32_t a, uint32_t c) {
    asm volatile("mbarrier.init.shared::cta.b64 [%0], %1;" :: "r"(a), "r"(c) : "memory");
}
__device__ __forceinline__ void mbar_expect(uint32_t a, uint32_t tx) {
    asm volatile("mbarrier.arrive.expect_tx.shared::cta.b64 _, [%0], %1;" :: "r"(a), "r"(tx) : "memory");
}
__device__ __forceinline__ void tma1d(uint32_t dst, const void* src, uint32_t bytes, uint32_t mbar) {
    asm volatile("cp.async.bulk.shared::cluster.global.mbarrier::complete_tx::bytes [%0], [%1], %2, [%3];"
                 :: "r"(dst), "l"(src), "r"(bytes), "r"(mbar) : "memory");
}
__device__ __forceinline__ void mbar_wait(uint32_t a, uint32_t ph) {
    uint32_t done = 0;
    while (!done) {
        asm volatile("{\n\t.reg .pred p;\n\t"
                     "mbarrier.try_wait.parity.acquire.cta.shared::cta.b64 p, [%1], %2;\n\t"
                     "selp.b32 %0, 1, 0, p;\n\t}"
                     : "=r"(done) : "r"(a), "r"(ph) : "memory");
    }
}
__device__ __forceinline__ float tanh_fast(float x) {
    float y; asm("tanh.approx.f32 %0, %1;" : "=f"(y) : "f"(x)); return y;
}
__device__ __forceinline__ void fma2(ull& a, ull w, ull b) {
    asm("fma.rn.f32x2 %0, %1, %2, %0;" : "+l"(a) : "l"(w), "l"(b));
}
__device__ __forceinline__ float unpadd(ull v) {
    unsigned l, h;
    asm("mov.b64 {%0, %1}, %2;" : "=r"(l), "=r"(h) : "l"(v));
    return __uint_as_float(l) + __uint_as_float(h);
}

// ---- prep: swizzle W[:,2:130] quarters + pack aux ----
__global__ void prep_kernel(const float* __restrict__ gW, const float* __restrict__ gB,
                            const float* __restrict__ gWf) {
    const int c = blockIdx.x;
    const float* src = gW + (size_t)c * (HH * 130);
    float* dw = g_Wq + (size_t)c * 16384;
    for (int t = threadIdx.x; t < HH * 128; t += blockDim.x) {
        const int n = t >> 7, kp = t & 127;
        const int kq = kp >> 5, q = kp & 31;
        const int chunk = q >> 2, elem = q & 3;
        const int slot = (chunk + n) & 7;
        dw[kq * 4096 + n * 32 + slot * 4 + elem] = src[n * 130 + 2 + kp];
    }
    float* da = g_aux + (size_t)c * 512;
    for (int t = threadIdx.x; t < 512; t += blockDim.x) {
        const int j = t >> 7, n = t & 127;
        float v;
        if (j == 0)      v = src[n * 130 + 0];
        else if (j == 1) v = src[n * 130 + 1];
        else if (j == 2) v = gB[c * HH + n];
        else             v = gWf[c * HH + n];
        da[t] = v;
    }
}

// ---- main persistent kernel ----
__global__ void __launch_bounds__(NTHR, 1)
rnn2d_kernel(const float* __restrict__ gS, const float* __restrict__ gBf,
             float* __restrict__ out)
{
    extern __shared__ unsigned char sb[];
    const uint32_t sbu = s2u(sb);
    const int tid = threadIdx.x, blk = blockIdx.x;
    const int n = tid & 127, kq = tid >> 7;
    const int lid = tid & 31, wid = tid >> 5;

    float4*   HV   = (float4*)(sb + OFF_HV);
    float*    PRE  = (float*)(sb + OFF_PRE);
    float*    INP  = (float*)(sb + OFF_INP);
    float4*   RED2 = (float4*)(sb + OFF_RED2);
    float4*   RED3 = (float4*)(sb + OFF_RED3);
    uint4*    SB4  = (uint4*)(sb + OFF_SB4);

    // init
    const float* gs = gS + (size_t)blk * SPB * NCELL;
    if (tid < SPB * LL) {
        const int sm = tid >> 5, row = tid & 31;
        const float* rp = gs + sm * NCELL + row * LL;
        uint32_t bits = 0;
        #pragma unroll
        for (int j = 0; j < LL; ++j) bits |= (rp[j] > 0.5f ? 1u : 0u) << j;
        ((uint32_t*)SB4)[row * 4 + sm] = bits;
    }
    for (int t = tid; t < LL * HH; t += NTHR) HV[t] = make_float4(0.f, 0.f, 0.f, 0.f);
    for (int t = tid; t < SPB * HH; t += NTHR) INP[t] = 0.f;

    const uint32_t mb0 = sbu + OFF_MBAR, mb1 = sbu + OFF_MBAR + 8;
    if (tid == 0) {
        mbar_init(mb0, 1);
        mbar_init(mb1, 1);
        asm volatile("fence.mbarrier_init.release.cluster;" ::: "memory");
        // pre-issue ONLY cell 0 (loop prefetches c+1 at distance 1)
        mbar_expect(mb0, TX_BYTES);
        tma1d(sbu + OFF_W, g_Wq, W_STAGE_BYTES, mb0);
        tma1d(sbu + OFF_AUX, g_aux, AUX_STAGE_BYTES, mb0);
    }
    __syncthreads();

    for (int c = 0; c < NCELL; ++c) {
        const int st = c & 1;
        const int r = c >> 5, j = c & 31;
        const int col = (r & 1) ? (LL - 1 - j) : j;

        // prefetch c+1 into the other stage
        if (tid == 0 && c + 1 < NCELL) {
            const int cn = c + 1, rn = cn >> 5, jn = cn & 31;
            const int coln = (rn & 1) ? (LL - 1 - jn) : jn;
            const int celln = (rn << 5) + coln;
            const uint32_t mb = st ? mb0 : mb1;
            mbar_expect(mb, TX_BYTES);
            tma1d(sbu + OFF_W + (st ^ 1) * W_STAGE_BYTES, g_Wq + (size_t)celln * 16384, W_STAGE_BYTES, mb);
            tma1d(sbu + OFF_AUX + (st ^ 1) * AUX_STAGE_BYTES, g_aux + (size_t)celln * 512, AUX_STAGE_BYTES, mb);
        }
        mbar_wait(st ? mb1 : mb0, (c >> 1) & 1);

        // ---- phase 1: quarter-matvec (all 512 threads) ----
        const unsigned char* wb = sb + OFF_W + st * W_STAGE_BYTES + kq * 16384 + n * 128;
        const unsigned char* ib = sb + OFF_INP + kq * 128;
        ull a0 = 0ull, a1 = 0ull, a2 = 0ull, a3 = 0ull;
        #pragma unroll
        for (int i = 0; i < 8; ++i) {
            const u64x2 w  = *(const u64x2*)(wb + (((i + n) & 7) << 4));
            const u64x2 x0 = *(const u64x2*)(ib + 0 * 512 + i * 16);
            const u64x2 x1 = *(const u64x2*)(ib + 1 * 512 + i * 16);
            const u64x2 x2 = *(const u64x2*)(ib + 2 * 512 + i * 16);
            const u64x2 x3 = *(const u64x2*)(ib + 3 * 512 + i * 16);
            fma2(a0, w.x, x0.x); fma2(a0, w.y, x0.y);
            fma2(a1, w.x, x1.x); fma2(a1, w.y, x1.y);
            fma2(a2, w.x, x2.x); fma2(a2, w.y, x2.y);
            fma2(a3, w.x, x3.x); fma2(a3, w.y, x3.y);
        }
        RED2[kq * 128 + n] = make_float4(unpadd(a0), unpadd(a1), unpadd(a2), unpadd(a3));
        __syncthreads();   // BAR1

        // ---- phase 2 ----
        if (tid < 4 && c > 0) {
            const int pc = c - 1, pr = pc >> 5, pj = pc & 31;
            const int pcol = (pr & 1) ? (LL - 1 - pj) : pj;
            const float4 q0 = RED3[(pc & 1) * 4 + 0], q1 = RED3[(pc & 1) * 4 + 1];
            const float4 q2 = RED3[(pc & 1) * 4 + 2], q3 = RED3[(pc & 1) * 4 + 3];
            const float* f0 = &q0.x; const float* f1 = &q1.x;
            const float* f2 = &q2.x; const float* f3 = &q3.x;
            PRE[((pr << 5) + pcol) * 4 + tid] = f0[tid] + f1[tid] + f2[tid] + f3[tid];
        }
        if (tid < 128) {
            const float4 z0 = RED2[0 * 128 + n], z1 = RED2[1 * 128 + n];
            const float4 z2 = RED2[2 * 128 + n], z3 = RED2[3 * 128 + n];
            const float* AUX = (const float*)(sb + OFF_AUX + st * AUX_STAGE_BYTES);
            const float w0 = AUX[n], w1 = AUX[128 + n];
            const float bb2 = 2.f * AUX[256 + n], wf = AUX[384 + n];
            const int colprev = (r & 1) ? (col + 1) : (col - 1);
            const uint4 brow = SB4[r];
            const uint4 arow = (r > 0) ? SB4[r - 1] : make_uint4(0, 0, 0, 0);
            float e[4];
            const uint32_t* bp = &brow.x; const uint32_t* ap = &arow.x;
            #pragma unroll
            for (int s = 0; s < SPB; ++s) {
                const float xh = (j == 0) ? 0.f : (float)((bp[s] >> colprev) & 1u);
                const float xv = (r == 0) ? 0.f : (float)((ap[s] >> col) & 1u);
                e[s] = xh + xv;
            }
            float h[4];
            h[0] = tanh_fast(z0.x + z1.x + z2.x + z3.x + bb2 + w0 * e[0] + w1 * (2.f - e[0]));
            h[1] = tanh_fast(z0.y + z1.y + z2.y + z3.y + bb2 + w0 * e[1] + w1 * (2.f - e[1]));
            h[2] = tanh_fast(z0.z + z1.z + z2.z + z3.z + bb2 + w0 * e[2] + w1 * (2.f - e[2]));
            h[3] = tanh_fast(z0.w + z1.w + z2.w + z3.w + bb2 + w0 * e[3] + w1 * (2.f - e[3]));

            float p0 = wf * h[0], p1 = wf * h[1], p2 = wf * h[2], p3 = wf * h[3];
            #pragma unroll
            for (int o = 16; o; o >>= 1) {
                p0 += __shfl_xor_sync(0xffffffffu, p0, o);
                p1 += __shfl_xor_sync(0xffffffffu, p1, o);
                p2 += __shfl_xor_sync(0xffffffffu, p2, o);
                p3 += __shfl_xor_sync(0xffffffffu, p3, o);
            }
            if (lid == 0) RED3[(c & 1) * 4 + wid] = make_float4(p0, p1, p2, p3);

            const float4 hvv = make_float4(h[0], h[1], h[2], h[3]);
            HV[col * 128 + n] = hvv;
            if (c + 1 < NCELL) {
                const int cn = c + 1, rn = cn >> 5, jn = cn & 31;
                const int coln = (rn & 1) ? (LL - 1 - jn) : jn;
                float4 v = hvv;
                if (jn != 0) {
                    const float4 t = HV[coln * 128 + n];
                    v = make_float4(h[0] + t.x, h[1] + t.y, h[2] + t.z, h[3] + t.w);
                }
                INP[0 * 128 + n] = v.x;
                INP[1 * 128 + n] = v.y;
                INP[2 * 128 + n] = v.z;
                INP[3 * 128 + n] = v.w;
            }
        }
        __syncthreads();   // BAR2
    }

    // final gather for last cell
    if (tid < 4) {
        const int pc = NCELL - 1;
        const int pr = pc >> 5, pj = pc & 31;
        const int pcol = (pr & 1) ? (LL - 1 - pj) : pj;
        const float4 q0 = RED3[(pc & 1) * 4 + 0], q1 = RED3[(pc & 1) * 4 + 1];
        const float4 q2 = RED3[(pc & 1) * 4 + 2], q3 = RED3[(pc & 1) * 4 + 3];
        const float* f0 = &q0.x; const float* f1 = &q1.x;
        const float* f2 = &q2.x; const float* f3 = &q3.x;
        PRE[((pr << 5) + pcol) * 4 + tid] = f0[tid] + f1[tid] + f2[tid] + f3[tid];
    }
    __syncthreads();

    // ---- bulk log-prob ----
    float lp0 = 0.f, lp1 = 0.f, lp2 = 0.f, lp3 = 0.f;
    for (int c = tid; c < NCELL; c += NTHR) {
        const float bfv = __ldg(gBf + c);
        const float4 pr = *(const float4*)&PRE[c * 4];
        const int row = c >> 5, bit = c & 31;
        const uint4 bits = SB4[row];
        float z, xh, m;
        z = pr.x + bfv; xh = 1.f / (1.f + __expf(-z));
        m = (float)((bits.x >> bit) & 1u);
        lp0 += m * __logf(xh + EPSF) + (1.f - m) * __logf(1.f - xh + EPSF);
        z = pr.y + bfv; xh = 1.f / (1.f + __expf(-z));
        m = (float)((bits.y >> bit) & 1u);
        lp1 += m * __logf(xh + EPSF) + (1.f - m) * __logf(1.f - xh + EPSF);
        z = pr.z + bfv; xh = 1.f / (1.f + __expf(-z));
        m = (float)((bits.z >> bit) & 1u);
        lp2 += m * __logf(xh + EPSF) + (1.f - m) * __logf(1.f - xh + EPSF);
        z = pr.w + bfv; xh = 1.f / (1.f + __expf(-z));
        m = (float)((bits.w >> bit) & 1u);
        lp3 += m * __logf(xh + EPSF) + (1.f - m) * __logf(1.f - xh + EPSF);
    }
    #pragma unroll
    for (int o = 16; o; o >>= 1) {
        lp0 += __shfl_xor_sync(0xffffffffu, lp0, o);
        lp1 += __shfl_xor_sync(0xffffffffu, lp1, o);
        lp2 += __shfl_xor_sync(0xffffffffu, lp2, o);
        lp3 += __shfl_xor_sync(0xffffffffu, lp3, o);
    }
    if (lid == 0) RED2[wid] = make_float4(lp0, lp1, lp2, lp3);
    __syncthreads();
    if (tid < 4) {
        float acc = 0.f;
        #pragma unroll
        for (int w = 0; w < 16; ++w) {
            const float4 q = RED2[w];
            const float* f = &q.x;
            acc += f[tid];
        }
        out[blk * SPB + tid] = acc;
    }
}

extern "C" void kernel_launch(void* const* d_in, const int* in_sizes, int n_in,
                              void* d_out, int out_size) {
    const float* samples = (const float*)d_in[0];
    const float* W1      = (const float*)d_in[1];
    const float* b1      = (const float*)d_in[2];
    const float* Wf      = (const float*)d_in[3];
    const float* bf      = (const float*)d_in[4];
    float* out = (float*)d_out;

    prep_kernel<<<NCELL, 256>>>(W1, b1, Wf);

    cudaFuncSetAttribute(rnn2d_kernel, cudaFuncAttributeMaxDynamicSharedMemorySize, (int)SMEM_SZ);
    rnn2d_kernel<<<NBLK, NTHR, SMEM_SZ>>>(samples, bf, out);
}

// round 9
// speedup vs baseline: 2.7422x; 2.7422x over previous
#include <cuda_runtime.h>
#include <cuda_bf16.h>
#include <cstdint>
#include <cstddef>

#define LL 32
#define HH 128
#define KD 130
#define KP 136            // padded bf16 row; 272B stride -> conflict-free LDS.128
#define SPB 2
#define NBLK 256
#define NTHR 128
#define NCELL 1024
#define EPSF 1e-8f
#define W_BYTES  (HH * KP * 2u)   // 34816
#define SM_BYTES 512u
#define TX_BYTES (W_BYTES + 2u * SM_BYTES)

typedef unsigned long long ull;

__device__ unsigned short g_Wb[(size_t)NCELL * HH * KP];   // bf16, padded

struct __align__(16) Smem {
    unsigned short W[2][HH * KP];   // 69632
    float bvec[2][HH];              //  1024
    float wfvec[2][HH];             //  1024
    float2 hv[LL][HH];              // 32768
    float2 inp[2][KP];              //  2176  ([k] = (s0,s1))
    float red[2][4][SPB];           //    64
    uint32_t sbits[SPB][LL];        //   256
    ull mbar[2];                    //    16
};                                  // ~107 KB -> 2 CTAs/SM

__device__ __forceinline__ uint32_t s2u(const void* p) {
    return (uint32_t)__cvta_generic_to_shared(p);
}
__device__ __forceinline__ void mbar_init(uint32_t a, uint32_t c) {
    asm volatile("mbarrier.init.shared::cta.b64 [%0], %1;" :: "r"(a), "r"(c) : "memory");
}
__device__ __forceinline__ void mbar_expect(uint32_t a, uint32_t tx) {
    asm volatile("mbarrier.arrive.expect_tx.shared::cta.b64 _, [%0], %1;" :: "r"(a), "r"(tx) : "memory");
}
__device__ __forceinline__ void tma1d(uint32_t dst, const void* src, uint32_t bytes, uint32_t mbar) {
    asm volatile("cp.async.bulk.shared::cluster.global.mbarrier::complete_tx::bytes [%0], [%1], %2, [%3];"
                 :: "r"(dst), "l"(src), "r"(bytes), "r"(mbar) : "memory");
}
__device__ __forceinline__ void mbar_wait(uint32_t a, uint32_t ph) {
    uint32_t done = 0;
    while (!done) {
        asm volatile("{\n\t.reg .pred p;\n\t"
                     "mbarrier.try_wait.parity.acquire.cta.shared::cta.b64 p, [%1], %2;\n\t"
                     "selp.b32 %0, 1, 0, p;\n\t}"
                     : "=r"(done) : "r"(a), "r"(ph) : "memory");
    }
}
__device__ __forceinline__ float tanh_fast(float x) {
    float y; asm("tanh.approx.f32 %0, %1;" : "=f"(y) : "f"(x)); return y;
}
__device__ __forceinline__ float bflo(uint32_t u) { return __uint_as_float(u << 16); }
__device__ __forceinline__ float bfhi(uint32_t u) { return __uint_as_float(u & 0xffff0000u); }

// ---- prep: fp32 W -> bf16, rows 130 -> 136 ----
__global__ void prep_kernel(const float* __restrict__ gW) {
    const int c = blockIdx.x;
    const float* src = gW + (size_t)c * (HH * KD);
    unsigned short* dst = g_Wb + (size_t)c * (HH * KP);
    for (int t = threadIdx.x; t < HH * KP; t += blockDim.x) {
        const int row = t / KP, col = t - row * KP;
        __nv_bfloat16 b = __float2bfloat16((col < KD) ? src[row * KD + col] : 0.f);
        dst[t] = *reinterpret_cast<unsigned short*>(&b);
    }
}

// ---- main persistent kernel: 2 samples/CTA, 2 CTAs/SM ----
__global__ void __launch_bounds__(NTHR, 2)
rnn2d_kernel(const float* __restrict__ gS, const float* __restrict__ gB,
             const float* __restrict__ gWf, const float* __restrict__ gBf,
             float* __restrict__ out)
{
    extern __shared__ unsigned char smem_raw[];
    Smem& s = *reinterpret_cast<Smem*>(smem_raw);
    const int tid = threadIdx.x;
    const int blk = blockIdx.x;
    const int lid = tid & 31, wid = tid >> 5;
    const int n = tid;

    // ---- init ----
    const float* gs = gS + (size_t)blk * SPB * NCELL;
    if (tid < SPB * LL) {
        const int sm = tid >> 5, row = tid & 31;
        const float* rp = gs + sm * NCELL + row * LL;
        uint32_t bits = 0;
        #pragma unroll
        for (int j = 0; j < LL; ++j) bits |= (rp[j] > 0.5f ? 1u : 0u) << j;
        s.sbits[sm][row] = bits;
    }
    for (int t = tid; t < LL * HH; t += NTHR) ((float2*)s.hv)[t] = make_float2(0.f, 0.f);
    for (int t = tid; t < 2 * KP; t += NTHR) ((float2*)s.inp)[t] = make_float2(0.f, 0.f);
    __syncthreads();
    if (tid == 0) s.inp[0][1] = make_float2(2.f, 2.f);   // (1-xh)+(1-xv) at cell 0

    const uint32_t mb0 = s2u(&s.mbar[0]);
    const uint32_t mb1 = s2u(&s.mbar[1]);
    if (tid == 0) {
        mbar_init(mb0, 1);
        mbar_init(mb1, 1);
        asm volatile("fence.mbarrier_init.release.cluster;" ::: "memory");
        mbar_expect(mb0, TX_BYTES);
        tma1d(s2u(&s.W[0][0]),     g_Wb, W_BYTES,  mb0);
        tma1d(s2u(&s.bvec[0][0]),  gB,   SM_BYTES, mb0);
        tma1d(s2u(&s.wfvec[0][0]), gWf,  SM_BYTES, mb0);
    }
    __syncthreads();

    float lp = 0.f;

    for (int c = 0; c < NCELL; ++c) {
        const int buf = c & 1;
        const int r = c >> 5, j = c & 31;
        const int col = (r & 1) ? (LL - 1 - j) : j;
        const int cell = (r << 5) + col;

        if (tid == 0 && c + 1 < NCELL) {
            const int cn = c + 1, rn = cn >> 5, jn = cn & 31;
            const int coln = (rn & 1) ? (LL - 1 - jn) : jn;
            const int celln = (rn << 5) + coln;
            const uint32_t mb = buf ? mb0 : mb1;
            mbar_expect(mb, TX_BYTES);
            tma1d(s2u(&s.W[buf ^ 1][0]),     g_Wb + (size_t)celln * HH * KP, W_BYTES,  mb);
            tma1d(s2u(&s.bvec[buf ^ 1][0]),  gB  + celln * HH,               SM_BYTES, mb);
            tma1d(s2u(&s.wfvec[buf ^ 1][0]), gWf + celln * HH,               SM_BYTES, mb);
        }
        mbar_wait(buf ? mb1 : mb0, (c >> 1) & 1);

        // ---- matvec: thread = neuron; bf16 weights, fp32 accumulate, 2 samples ----
        const unsigned short* Wr = &s.W[buf][n * KP];
        const float4* ip4 = (const float4*)&s.inp[buf][0];   // ip4[t] = (k=2t:(s0,s1), k=2t+1:(s0,s1))
        float a0 = 0.f, a1 = 0.f, a2 = 0.f, a3 = 0.f;
        float c0 = 0.f, c1 = 0.f, c2 = 0.f, c3 = 0.f;
        #pragma unroll
        for (int i = 0; i < KP / 8; ++i) {
            const uint4 wp = *(const uint4*)(Wr + i * 8);
            const float4 q0 = ip4[i * 4 + 0];
            const float4 q1 = ip4[i * 4 + 1];
            const float4 q2 = ip4[i * 4 + 2];
            const float4 q3 = ip4[i * 4 + 3];
            float w;
            w = bflo(wp.x); a0 += w * q0.x; c0 += w * q0.y;
            w = bfhi(wp.x); a1 += w * q0.z; c1 += w * q0.w;
            w = bflo(wp.y); a2 += w * q1.x; c2 += w * q1.y;
            w = bfhi(wp.y); a3 += w * q1.z; c3 += w * q1.w;
            w = bflo(wp.z); a0 += w * q2.x; c0 += w * q2.y;
            w = bfhi(wp.z); a1 += w * q2.z; c1 += w * q2.w;
            w = bflo(wp.w); a2 += w * q3.x; c2 += w * q3.y;
            w = bfhi(wp.w); a3 += w * q3.z; c3 += w * q3.w;
        }
        const float bi2 = 2.f * s.bvec[buf][n];
        const float h0 = tanh_fast((a0 + a1) + (a2 + a3) + bi2);
        const float h1 = tanh_fast((c0 + c1) + (c2 + c3) + bi2);

        // fc-head partials
        const float wfi = s.wfvec[buf][n];
        float p0 = wfi * h0, p1 = wfi * h1;
        #pragma unroll
        for (int o = 16; o; o >>= 1) {
            p0 += __shfl_xor_sync(0xffffffffu, p0, o);
            p1 += __shfl_xor_sync(0xffffffffu, p1, o);
        }
        if (lid == 0) {
            s.red[buf][wid][0] = p0;
            s.red[buf][wid][1] = p1;
        }

        // hv + next-cell input
        const float2 hvv = make_float2(h0, h1);
        s.hv[col][n] = hvv;
        if (c + 1 < NCELL) {
            const int cn = c + 1, rn = cn >> 5, jn = cn & 31;
            const int coln = (rn & 1) ? (LL - 1 - jn) : jn;
            float2 v = hvv;
            if (jn != 0) {
                const float2 t = s.hv[coln][n];
                v = make_float2(h0 + t.x, h1 + t.y);
            }
            s.inp[buf ^ 1][2 + n] = v;
            if (tid == 0) {
                float2 e0, e1;
                #pragma unroll
                for (int si = 0; si < SPB; ++si) {
                    const float xh = (jn == 0) ? 0.f : (float)((s.sbits[si][rn] >> col) & 1u);
                    const float xv = (rn == 0) ? 0.f : (float)((s.sbits[si][rn - 1] >> coln) & 1u);
                    ((float*)&e0)[si] = xh + xv;
                    ((float*)&e1)[si] = 2.f - xh - xv;
                }
                s.inp[buf ^ 1][0] = e0;
                s.inp[buf ^ 1][1] = e1;
            }
        }
        __syncthreads();

        // inline log-prob (2 threads; hidden by the co-resident CTA)
        if (tid < SPB) {
            const float dot = s.red[buf][0][tid] + s.red[buf][1][tid]
                            + s.red[buf][2][tid] + s.red[buf][3][tid];
            const float pre = dot + __ldg(gBf + cell);
            const float xhat = 1.f / (1.f + __expf(-pre));
            const float m = (float)((s.sbits[tid][r] >> col) & 1u);
            lp += m * __logf(xhat + EPSF) + (1.f - m) * __logf(1.f - xhat + EPSF);
        }
    }

    if (tid < SPB) out[blk * SPB + tid] = lp;
}

extern "C" void kernel_launch(void* const* d_in, const int* in_sizes, int n_in,
                              void* d_out, int out_size) {
    const float* samples = (const float*)d_in[0];
    const float* W1      = (const float*)d_in[1];
    const float* b1      = (const float*)d_in[2];
    const float* Wf      = (const float*)d_in[3];
    const float* bf      = (const float*)d_in[4];
    float* out = (float*)d_out;

    prep_kernel<<<NCELL, 256>>>(W1);

    const size_t smem = sizeof(Smem);
    cudaFuncSetAttribute(rnn2d_kernel, cudaFuncAttributeMaxDynamicSharedMemorySize, (int)smem);
    rnn2d_kernel<<<NBLK, NTHR, smem>>>(samples, b1, Wf, bf, out);
}